// round 13
// baseline (speedup 1.0000x reference)
#include <cuda_runtime.h>
#include <cuda_bf16.h>
#include <cuda_fp16.h>
#include <cstdint>
#include <math_constants.h>

// ---------------- problem constants ----------------
static constexpr int NN  = 40000;     // nodes
static constexpr int NE  = 1280000;   // edges
static constexpr int DF  = 1024;      // input feat
static constexpr int HID = 64;        // hidden
static constexpr int NC  = 40;        // classes

// ---------------- device scratch ----------------
__device__ float  g_H1[(size_t)NN * HID];   // x @ W1 (fp32, self-term)
__device__ __half g_H1h[(size_t)NN * HID];  // fp16 mirror for neighbor gathers
__device__ float  g_H2[(size_t)NN * NC];    // fp32 self-term
__device__ __half g_H2h[(size_t)NN * NC];   // fp16 mirror for gather2
__device__ float  g_dinv[NN];
__device__ int    g_deg[NN];                // in-degree (no self loop)
__device__ int    g_rowptr[NN];             // CSR start per node
__device__ int    g_cursor[NN];
__device__ int    g_rowtmp[NN];             // inclusive scan, pre-base
__device__ int    g_bsum[160];
__device__ int    g_bbase[160];
__device__ __align__(16) int2 g_edge[NE];   // (src, weight-bits) grouped by dst
__device__ __nv_bfloat16 g_W1h[(size_t)HID * DF];  // W1^T bf16, [n][k]

// ---------------- helpers ----------------
__device__ __forceinline__ uint32_t smem_to_u32(const void* p) {
    uint32_t a;
    asm("{ .reg .u64 t; cvta.to.shared.u64 t, %1; cvt.u32.u64 %0, t; }" : "=r"(a) : "l"(p));
    return a;
}
__device__ __forceinline__ uint32_t bfbits(__nv_bfloat16 h) {
    return (uint32_t)__bfloat16_as_ushort(h);
}
#define LDSM4(r, addr) \
    asm volatile("ldmatrix.sync.aligned.m8n8.x4.shared.b16 {%0,%1,%2,%3}, [%4];" \
                 : "=r"((r)[0]), "=r"((r)[1]), "=r"((r)[2]), "=r"((r)[3]) : "r"(addr))
__device__ __forceinline__ void mma16816(float* c, const uint32_t* a, uint32_t b0, uint32_t b1) {
    asm volatile(
        "mma.sync.aligned.m16n8k16.row.col.f32.bf16.bf16.f32 "
        "{%0,%1,%2,%3}, {%4,%5,%6,%7}, {%8,%9}, {%0,%1,%2,%3};"
        : "+f"(c[0]), "+f"(c[1]), "+f"(c[2]), "+f"(c[3])
        : "r"(a[0]), "r"(a[1]), "r"(a[2]), "r"(a[3]), "r"(b0), "r"(b1));
}

// ---------------- prep ----------------
__global__ void k_hist(const int* __restrict__ col) {
    int e = blockIdx.x * blockDim.x + threadIdx.x;
    if (e < NE) atomicAdd(&g_deg[col[e]], 1);
}
__global__ void k_wsplit(const float* __restrict__ W1) {
    int idx = blockIdx.x * blockDim.x + threadIdx.x;
    if (idx >= DF * HID) return;
    int k = idx >> 6, n = idx & 63;
    g_W1h[(size_t)n * DF + k] = __float2bfloat16(W1[idx]);
}

// ---------------- CSR build: 3-phase scan + fill ----------------
static constexpr int SCAN_NB = (NN + 255) / 256;  // 157
__global__ void k_scanA() {
    __shared__ int s[256];
    int i = blockIdx.x * 256 + threadIdx.x;
    int v = (i < NN) ? g_deg[i] : 0;
    s[threadIdx.x] = v;
    __syncthreads();
#pragma unroll
    for (int off = 1; off < 256; off <<= 1) {
        int t = (threadIdx.x >= off) ? s[threadIdx.x - off] : 0;
        __syncthreads();
        s[threadIdx.x] += t;
        __syncthreads();
    }
    if (i < NN) g_rowtmp[i] = s[threadIdx.x];
    if (threadIdx.x == 255) g_bsum[blockIdx.x] = s[255];
}
__global__ void k_scanB() {
    __shared__ int s[256];
    int v = (threadIdx.x < SCAN_NB) ? g_bsum[threadIdx.x] : 0;
    s[threadIdx.x] = v;
    __syncthreads();
#pragma unroll
    for (int off = 1; off < 256; off <<= 1) {
        int t = (threadIdx.x >= off) ? s[threadIdx.x - off] : 0;
        __syncthreads();
        s[threadIdx.x] += t;
        __syncthreads();
    }
    if (threadIdx.x < SCAN_NB) g_bbase[threadIdx.x] = s[threadIdx.x] - v;  // exclusive
}
__global__ void k_scanC() {  // rowptr/cursor + dinv fused
    int i = blockIdx.x * 256 + threadIdx.x;
    if (i >= NN) return;
    int d = g_deg[i];
    int start = g_rowtmp[i] + g_bbase[blockIdx.x] - d;
    g_rowptr[i] = start;
    g_cursor[i] = start;
    g_dinv[i] = rsqrtf((float)(d + 1));  // +1 self loop
}
__global__ void k_fill(const int* __restrict__ row, const int* __restrict__ col) {
    int e = blockIdx.x * blockDim.x + threadIdx.x;
    if (e >= NE) return;
    int r = __ldg(row + e), c = __ldg(col + e);
    int p = atomicAdd(&g_cursor[c], 1);
    float w = __ldg(g_dinv + r) * __ldg(g_dinv + c);
    g_edge[p] = make_int2(r, __float_as_int(w));
}

// ---------------- GEMM1: single-pass bf16 mma, M-tile 64, DOUBLE-BUFFERED ----------------
static constexpr int SA_STRIDE = 72;                 // bf16 elems per row (144B)
static constexpr int O_A = 0;
static constexpr int O_B = 64 * SA_STRIDE * 2;       // 9216
static constexpr int BUF_SZ = O_B + 64 * SA_STRIDE * 2;  // 18432
static constexpr int SM_TOTAL = 2 * BUF_SZ;          // 36864

__global__ void __launch_bounds__(256, 2) k_gemm1(const float* __restrict__ x) {
    extern __shared__ char sm[];
    const uint32_t smb = smem_to_u32(sm);
    const int t = threadIdx.x;
    const int lane = t & 31, w = t >> 5;
    const int strip = w >> 1, nhalf = w & 1;
    const int m0 = blockIdx.x * 64;

    const int r0t = t >> 4;
    const int c4  = t & 15;
    const float4* xb = (const float4*)x;
    size_t rbase[4];
    uint32_t aDst[4];
#pragma unroll
    for (int i = 0; i < 4; i++) {
        int rowg = m0 + r0t + 16 * i;
        rbase[i] = (size_t)rowg * 256 + c4;  // float4 units
        aDst[i] = (uint32_t)((r0t + 16 * i) * (SA_STRIDE * 2) + c4 * 8);
    }
    const uint32_t aLd = smb +
        (uint32_t)((strip * 16 + (lane & 7) + ((lane >> 3) & 1) * 8) * (SA_STRIDE * 2) +
                   (lane >> 4) * 16);
    const uint32_t bLd = smb +
        (uint32_t)((nhalf * 32 + ((lane >> 4) * 8) + (lane & 7)) * (SA_STRIDE * 2) +
                   ((lane >> 3) & 1) * 16);

    float acc[4][4];
#pragma unroll
    for (int j = 0; j < 4; j++)
#pragma unroll
        for (int q = 0; q < 4; q++) acc[j][q] = 0.f;

    // prologue: chunk-0 operands into registers
    float4 pf[4];
    uint2 bh[4];
#pragma unroll
    for (int i = 0; i < 4; i++) pf[i] = __ldg(xb + rbase[i]);
#pragma unroll
    for (int j = 0; j < 4; j++) {
        int lin = t + j * 256;
        int n = lin >> 4, q = lin & 15;
        bh[j] = __ldg((const uint2*)(g_W1h + (size_t)n * DF + q * 4));
    }

    for (int kc = 0; kc < 16; kc++) {
        const uint32_t buf = (uint32_t)((kc & 1) * BUF_SZ);

        // ---- convert & store A chunk kc (bf16, single pass) ----
#pragma unroll
        for (int i = 0; i < 4; i++) {
            float4 v = pf[i];
            __nv_bfloat16 hx = __float2bfloat16(v.x), hy = __float2bfloat16(v.y);
            __nv_bfloat16 hz = __float2bfloat16(v.z), hw = __float2bfloat16(v.w);
            *(uint2*)(sm + buf + O_A + aDst[i]) =
                make_uint2(bfbits(hx) | (bfbits(hy) << 16), bfbits(hz) | (bfbits(hw) << 16));
        }
        // ---- store B chunk kc ----
#pragma unroll
        for (int j = 0; j < 4; j++) {
            int lin = t + j * 256;
            int n = lin >> 4, q = lin & 15;
            *(uint2*)(sm + buf + O_B + (uint32_t)(n * (SA_STRIDE * 2) + q * 8)) = bh[j];
        }
        __syncthreads();

        // ---- issue chunk kc+1 global loads (latency hides under MMA) ----
        if (kc < 15) {
#pragma unroll
            for (int i = 0; i < 4; i++)
                pf[i] = __ldg(xb + rbase[i] + (kc + 1) * 16);
#pragma unroll
            for (int j = 0; j < 4; j++) {
                int lin = t + j * 256;
                int n = lin >> 4, q = lin & 15;
                bh[j] = __ldg((const uint2*)(g_W1h + (size_t)n * DF + (kc + 1) * 64 + q * 4));
            }
        }

        // ---- MMA on chunk kc: 4 k16 steps x 2 jp (16 n each), single pass ----
#pragma unroll
        for (int ks = 0; ks < 4; ks++) {
            uint32_t ah[4];
            LDSM4(ah, buf + aLd + O_A + ks * 32);
#pragma unroll
            for (int jp = 0; jp < 2; jp++) {
                uint32_t vh[4];
                LDSM4(vh, buf + bLd + O_B + (uint32_t)(jp * (16 * SA_STRIDE * 2) + ks * 32));
                mma16816(acc[2 * jp],     ah, vh[0], vh[1]);
                mma16816(acc[2 * jp + 1], ah, vh[2], vh[3]);
            }
        }
        // no second barrier: next iteration writes the OTHER buffer
    }

    // ---- epilogue: fp32 + fp16 mirror ----
    const int g = lane >> 2, tig = lane & 3;
    const int r0 = m0 + strip * 16 + g;
    const int r1 = r0 + 8;
#pragma unroll
    for (int nt = 0; nt < 4; nt++) {
        int c = nhalf * 32 + nt * 8 + tig * 2;
        *(float2*)(g_H1 + (size_t)r0 * 64 + c) = make_float2(acc[nt][0], acc[nt][1]);
        *(float2*)(g_H1 + (size_t)r1 * 64 + c) = make_float2(acc[nt][2], acc[nt][3]);
        *(__half2*)(g_H1h + (size_t)r0 * 64 + c) = __floats2half2_rn(acc[nt][0], acc[nt][1]);
        *(__half2*)(g_H1h + (size_t)r1 * 64 + c) = __floats2half2_rn(acc[nt][2], acc[nt][3]);
    }
}

// ---------------- gather1 + relu + bias + GEMM2 fused (warp per node) ----------------
// int4-paired edge loads (2 edges/LDG); neighbor rows fp16; self + math fp32.
__global__ void __launch_bounds__(256) k_gather1(const float* __restrict__ b1,
                                                 const float* __restrict__ W2) {
    __shared__ float sW[HID * NC];   // 10240 B
    __shared__ float sO[8][HID];     // 2048 B
    for (int i = threadIdx.x; i < HID * NC; i += 256) sW[i] = __ldg(W2 + i);
    __syncthreads();

    const int w = threadIdx.x >> 5, lane = threadIdx.x & 31;
    const int n = blockIdx.x * 8 + w;

    float di = __ldg(g_dinv + n);
    float2 acc = __ldg((const float2*)(g_H1 + (size_t)n * 64) + lane);
    acc.x *= di * di; acc.y *= di * di;

    const int start = __ldg(g_rowptr + n);
    const int cnt   = __ldg(g_deg + n);
    int i = 0;
    // peel to 16B alignment (g_edge aligned 16; need even element index)
    if ((start & 1) && cnt > 0) {
        int2 e = __ldg(g_edge + start);
        __half2 v = __ldg((const __half2*)(g_H1h + (size_t)e.x * 64) + lane);
        float wt = __int_as_float(e.y);
        float2 f = __half22float2(v);
        acc.x = fmaf(wt, f.x, acc.x); acc.y = fmaf(wt, f.y, acc.y);
        i = 1;
    }
    const int4* ep4 = (const int4*)(g_edge + start + i);
    const int nb = (cnt - i) >> 3;
    for (int b = 0; b < nb; b++) {
        int4 p[4];
#pragma unroll
        for (int u = 0; u < 4; u++) p[u] = __ldg(ep4 + b * 4 + u);
        __half2 v[8];
#pragma unroll
        for (int u = 0; u < 4; u++) {
            v[2 * u]     = __ldg((const __half2*)(g_H1h + (size_t)p[u].x * 64) + lane);
            v[2 * u + 1] = __ldg((const __half2*)(g_H1h + (size_t)p[u].z * 64) + lane);
        }
#pragma unroll
        for (int u = 0; u < 4; u++) {
            float w0 = __int_as_float(p[u].y), w1 = __int_as_float(p[u].w);
            float2 f0 = __half22float2(v[2 * u]), f1 = __half22float2(v[2 * u + 1]);
            acc.x = fmaf(w0, f0.x, acc.x); acc.y = fmaf(w0, f0.y, acc.y);
            acc.x = fmaf(w1, f1.x, acc.x); acc.y = fmaf(w1, f1.y, acc.y);
        }
    }
    for (i += nb * 8; i < cnt; i++) {
        int2 e = __ldg(g_edge + start + i);
        __half2 v = __ldg((const __half2*)(g_H1h + (size_t)e.x * 64) + lane);
        float wt = __int_as_float(e.y);
        float2 f = __half22float2(v);
        acc.x = fmaf(wt, f.x, acc.x); acc.y = fmaf(wt, f.y, acc.y);
    }
    float2 b = __ldg((const float2*)b1 + lane);
    sO[w][lane * 2]     = fmaxf(acc.x + b.x, 0.f);
    sO[w][lane * 2 + 1] = fmaxf(acc.y + b.y, 0.f);
    __syncwarp();

    if (lane < 20) {
        float h0 = 0.f, h1 = 0.f;
        const float* o = sO[w];
#pragma unroll
        for (int k = 0; k < HID; k++) {
            float ov = o[k];
            h0 = fmaf(ov, sW[k * NC + 2 * lane],     h0);
            h1 = fmaf(ov, sW[k * NC + 2 * lane + 1], h1);
        }
        *(float2*)(g_H2 + (size_t)n * NC + lane * 2) = make_float2(h0, h1);
        *(__half2*)(g_H2h + (size_t)n * NC + lane * 2) = __floats2half2_rn(h0, h1);
    }
}

// ---------------- gather layer 2 + bias + log_softmax (warp per node) ----------------
__global__ void __launch_bounds__(256) k_gather2(const float* __restrict__ b2,
                                                 float* __restrict__ out) {
    const int w = threadIdx.x >> 5, lane = threadIdx.x & 31;
    const int n = blockIdx.x * 8 + w;
    const bool act = lane < 20;  // 20 lanes x 2 = 40 cols
    float di = __ldg(g_dinv + n);
    float2 acc = make_float2(0.f, 0.f);
    if (act) {
        acc = __ldg((const float2*)(g_H2 + (size_t)n * NC) + lane);
        acc.x *= di * di; acc.y *= di * di;
    }
    const int start = __ldg(g_rowptr + n);
    const int cnt   = __ldg(g_deg + n);
    int i = 0;
    if ((start & 1) && cnt > 0) {
        int2 e = __ldg(g_edge + start);
        if (act) {
            __half2 v = __ldg((const __half2*)(g_H2h + (size_t)e.x * NC) + lane);
            float wt = __int_as_float(e.y);
            float2 f = __half22float2(v);
            acc.x = fmaf(wt, f.x, acc.x); acc.y = fmaf(wt, f.y, acc.y);
        }
        i = 1;
    }
    const int4* ep4 = (const int4*)(g_edge + start + i);
    const int nb = (cnt - i) >> 3;
    for (int b = 0; b < nb; b++) {
        int4 p[4];
#pragma unroll
        for (int u = 0; u < 4; u++) p[u] = __ldg(ep4 + b * 4 + u);
        if (act) {
            __half2 v[8];
#pragma unroll
            for (int u = 0; u < 4; u++) {
                v[2 * u]     = __ldg((const __half2*)(g_H2h + (size_t)p[u].x * NC) + lane);
                v[2 * u + 1] = __ldg((const __half2*)(g_H2h + (size_t)p[u].z * NC) + lane);
            }
#pragma unroll
            for (int u = 0; u < 4; u++) {
                float w0 = __int_as_float(p[u].y), w1 = __int_as_float(p[u].w);
                float2 f0 = __half22float2(v[2 * u]), f1 = __half22float2(v[2 * u + 1]);
                acc.x = fmaf(w0, f0.x, acc.x); acc.y = fmaf(w0, f0.y, acc.y);
                acc.x = fmaf(w1, f1.x, acc.x); acc.y = fmaf(w1, f1.y, acc.y);
            }
        }
    }
    for (i += nb * 8; i < cnt; i++) {
        int2 e = __ldg(g_edge + start + i);
        if (act) {
            __half2 v = __ldg((const __half2*)(g_H2h + (size_t)e.x * NC) + lane);
            float wt = __int_as_float(e.y);
            float2 f = __half22float2(v);
            acc.x = fmaf(wt, f.x, acc.x); acc.y = fmaf(wt, f.y, acc.y);
        }
    }
    float2 z = make_float2(-CUDART_INF_F, -CUDART_INF_F);
    if (act) {
        float2 b = __ldg((const float2*)b2 + lane);
        z = make_float2(acc.x + b.x, acc.y + b.y);
    }
    float m = fmaxf(z.x, z.y);
#pragma unroll
    for (int off = 16; off; off >>= 1) m = fmaxf(m, __shfl_xor_sync(0xffffffffu, m, off));
    float s = act ? (__expf(z.x - m) + __expf(z.y - m)) : 0.f;
#pragma unroll
    for (int off = 16; off; off >>= 1) s += __shfl_xor_sync(0xffffffffu, s, off);
    float l = m + __logf(s);
    if (act)
        *(float2*)(out + (size_t)n * NC + lane * 2) = make_float2(z.x - l, z.y - l);
}

// ---------------- launch ----------------
extern "C" void kernel_launch(void* const* d_in, const int* in_sizes, int n_in,
                              void* d_out, int out_size) {
    const float* x  = (const float*)d_in[0];
    const int*   ei = (const int*)d_in[1];
    const float* W1 = (const float*)d_in[2];
    const float* b1 = (const float*)d_in[3];
    const float* W2 = (const float*)d_in[4];
    const float* b2 = (const float*)d_in[5];
    const int* row = ei;         // sources
    const int* col = ei + NE;    // targets
    float* out = (float*)d_out;

    static void* deg_ptr = nullptr;
    static cudaStream_t s2 = nullptr;
    static cudaEvent_t evFork = nullptr, evJoin = nullptr;
    if (!deg_ptr) {  // resolved on the (non-captured) correctness call
        cudaFuncSetAttribute(k_gemm1, cudaFuncAttributeMaxDynamicSharedMemorySize, SM_TOTAL);
        cudaGetSymbolAddress(&deg_ptr, g_deg);
        cudaStreamCreateWithFlags(&s2, cudaStreamNonBlocking);
        cudaEventCreateWithFlags(&evFork, cudaEventDisableTiming);
        cudaEventCreateWithFlags(&evJoin, cudaEventDisableTiming);
    }

    // fork: stream B runs wsplit + single-pass gemm1 (independent of CSR chain)
    cudaEventRecord(evFork, 0);
    cudaStreamWaitEvent(s2, evFork, 0);
    k_wsplit<<<(DF * HID + 255) / 256, 256, 0, s2>>>(W1);
    k_gemm1<<<NN / 64, 256, SM_TOTAL, s2>>>(x);
    cudaEventRecord(evJoin, s2);

    // default stream: CSR build chain
    cudaMemsetAsync(deg_ptr, 0, NN * sizeof(int));
    k_hist<<<(NE + 255) / 256, 256>>>(col);
    k_scanA<<<SCAN_NB, 256>>>();
    k_scanB<<<1, 256>>>();
    k_scanC<<<SCAN_NB, 256>>>();
    k_fill<<<(NE + 255) / 256, 256>>>(row, col);

    // join, then fused gather1+gemm2 and gather2
    cudaStreamWaitEvent(0, evJoin, 0);
    k_gather1<<<NN / 8, 256>>>(b1, W2);
    k_gather2<<<NN / 8, 256>>>(b2, out);
}

// round 14
// speedup vs baseline: 1.3299x; 1.3299x over previous
#include <cuda_runtime.h>
#include <cuda_bf16.h>
#include <cuda_fp16.h>
#include <cstdint>
#include <math_constants.h>

// ---------------- problem constants ----------------
static constexpr int NN  = 40000;     // nodes
static constexpr int NE  = 1280000;   // edges
static constexpr int DF  = 1024;      // input feat
static constexpr int HID = 64;        // hidden
static constexpr int NC  = 40;        // classes

// ---------------- device scratch ----------------
__device__ float  g_H1[(size_t)NN * HID];   // x @ W1 (fp32)
__device__ __half g_H1s[(size_t)NN * HID];  // fp16 dinv-scaled mirror (k_scale)
__device__ float  g_H2[(size_t)NN * NC];    // fp32 layer-2 pre-agg
__device__ __half g_H2s[(size_t)NN * NC];   // fp16 dinv-scaled mirror (gather1)
__device__ float  g_dinv[NN];
__device__ int    g_deg[NN];                // in-degree (no self loop)
__device__ int    g_rowptr[NN];             // CSR start per node
__device__ int    g_cursor[NN];
__device__ int    g_rowtmp[NN];             // inclusive scan, pre-base
__device__ int    g_bsum[160];
__device__ int    g_bbase[160];
__device__ __align__(16) int g_src[NE];     // src index only, grouped by dst
__device__ __nv_bfloat16 g_W1h[(size_t)HID * DF];  // W1^T hi, [n][k]
__device__ __nv_bfloat16 g_W1l[(size_t)HID * DF];  // W1^T lo, [n][k]

// ---------------- helpers ----------------
__device__ __forceinline__ uint32_t smem_to_u32(const void* p) {
    uint32_t a;
    asm("{ .reg .u64 t; cvta.to.shared.u64 t, %1; cvt.u32.u64 %0, t; }" : "=r"(a) : "l"(p));
    return a;
}
__device__ __forceinline__ uint32_t bfbits(__nv_bfloat16 h) {
    return (uint32_t)__bfloat16_as_ushort(h);
}
#define LDSM4(r, addr) \
    asm volatile("ldmatrix.sync.aligned.m8n8.x4.shared.b16 {%0,%1,%2,%3}, [%4];" \
                 : "=r"((r)[0]), "=r"((r)[1]), "=r"((r)[2]), "=r"((r)[3]) : "r"(addr))
__device__ __forceinline__ void mma16816(float* c, const uint32_t* a, uint32_t b0, uint32_t b1) {
    asm volatile(
        "mma.sync.aligned.m16n8k16.row.col.f32.bf16.bf16.f32 "
        "{%0,%1,%2,%3}, {%4,%5,%6,%7}, {%8,%9}, {%0,%1,%2,%3};"
        : "+f"(c[0]), "+f"(c[1]), "+f"(c[2]), "+f"(c[3])
        : "r"(a[0]), "r"(a[1]), "r"(a[2]), "r"(a[3]), "r"(b0), "r"(b1));
}

// ---------------- prep ----------------
__global__ void k_hist(const int* __restrict__ col) {
    int e = blockIdx.x * blockDim.x + threadIdx.x;
    if (e < NE) atomicAdd(&g_deg[col[e]], 1);
}
__global__ void k_wsplit(const float* __restrict__ W1) {
    int idx = blockIdx.x * blockDim.x + threadIdx.x;
    if (idx >= DF * HID) return;
    int k = idx >> 6, n = idx & 63;
    float w = W1[idx];
    __nv_bfloat16 hi = __float2bfloat16(w);
    float lo = w - __bfloat162float(hi);
    g_W1h[(size_t)n * DF + k] = hi;
    g_W1l[(size_t)n * DF + k] = __float2bfloat16(lo);
}

// ---------------- CSR build: 3-phase scan + fill ----------------
static constexpr int SCAN_NB = (NN + 255) / 256;  // 157
__global__ void k_scanA() {
    __shared__ int s[256];
    int i = blockIdx.x * 256 + threadIdx.x;
    int v = (i < NN) ? g_deg[i] : 0;
    s[threadIdx.x] = v;
    __syncthreads();
#pragma unroll
    for (int off = 1; off < 256; off <<= 1) {
        int t = (threadIdx.x >= off) ? s[threadIdx.x - off] : 0;
        __syncthreads();
        s[threadIdx.x] += t;
        __syncthreads();
    }
    if (i < NN) g_rowtmp[i] = s[threadIdx.x];
    if (threadIdx.x == 255) g_bsum[blockIdx.x] = s[255];
}
__global__ void k_scanB() {
    __shared__ int s[256];
    int v = (threadIdx.x < SCAN_NB) ? g_bsum[threadIdx.x] : 0;
    s[threadIdx.x] = v;
    __syncthreads();
#pragma unroll
    for (int off = 1; off < 256; off <<= 1) {
        int t = (threadIdx.x >= off) ? s[threadIdx.x - off] : 0;
        __syncthreads();
        s[threadIdx.x] += t;
        __syncthreads();
    }
    if (threadIdx.x < SCAN_NB) g_bbase[threadIdx.x] = s[threadIdx.x] - v;  // exclusive
}
__global__ void k_scanC() {  // rowptr/cursor + dinv fused
    int i = blockIdx.x * 256 + threadIdx.x;
    if (i >= NN) return;
    int d = g_deg[i];
    int start = g_rowtmp[i] + g_bbase[blockIdx.x] - d;
    g_rowptr[i] = start;
    g_cursor[i] = start;
    g_dinv[i] = rsqrtf((float)(d + 1));  // +1 self loop
}
__global__ void k_fill(const int* __restrict__ row, const int* __restrict__ col) {
    int e = blockIdx.x * blockDim.x + threadIdx.x;
    if (e >= NE) return;
    int r = __ldg(row + e), c = __ldg(col + e);
    int p = atomicAdd(&g_cursor[c], 1);
    g_src[p] = r;
}

// ---------------- GEMM1: mma.sync bf16 hi/lo, M-tile 64, DOUBLE-BUFFERED (round 12) ----------------
static constexpr int SA_STRIDE = 72;                 // bf16 elems per row (144B)
static constexpr int O_AH = 0;
static constexpr int O_AL = 64 * SA_STRIDE * 2;      // 9216
static constexpr int O_BH = O_AL * 2;                // 18432
static constexpr int O_BL = O_BH + 64 * SA_STRIDE * 2;  // 27648
static constexpr int BUF_SZ = O_BL + 64 * SA_STRIDE * 2; // 36864
static constexpr int SM_TOTAL = 2 * BUF_SZ;          // 73728

__global__ void __launch_bounds__(256, 2) k_gemm1(const float* __restrict__ x) {
    extern __shared__ char sm[];
    const uint32_t smb = smem_to_u32(sm);
    const int t = threadIdx.x;
    const int lane = t & 31, w = t >> 5;
    const int strip = w >> 1, nhalf = w & 1;
    const int m0 = blockIdx.x * 64;

    const int r0t = t >> 4;
    const int c4  = t & 15;
    const float4* xb = (const float4*)x;
    size_t rbase[4];
    uint32_t aDst[4];
#pragma unroll
    for (int i = 0; i < 4; i++) {
        int rowg = m0 + r0t + 16 * i;
        rbase[i] = (size_t)rowg * 256 + c4;  // float4 units
        aDst[i] = (uint32_t)((r0t + 16 * i) * (SA_STRIDE * 2) + c4 * 8);
    }
    const uint32_t aLd = smb +
        (uint32_t)((strip * 16 + (lane & 7) + ((lane >> 3) & 1) * 8) * (SA_STRIDE * 2) +
                   (lane >> 4) * 16);
    const uint32_t bLd = smb +
        (uint32_t)((nhalf * 32 + ((lane >> 4) * 8) + (lane & 7)) * (SA_STRIDE * 2) +
                   ((lane >> 3) & 1) * 16);

    float acc[4][4];
#pragma unroll
    for (int j = 0; j < 4; j++)
#pragma unroll
        for (int q = 0; q < 4; q++) acc[j][q] = 0.f;

    // prologue: chunk-0 operands into registers
    float4 pf[4];
    uint2 bh[4], bl[4];
#pragma unroll
    for (int i = 0; i < 4; i++) pf[i] = __ldg(xb + rbase[i]);
#pragma unroll
    for (int j = 0; j < 4; j++) {
        int lin = t + j * 256;
        int n = lin >> 4, q = lin & 15;
        size_t src = (size_t)n * DF + q * 4;
        bh[j] = __ldg((const uint2*)(g_W1h + src));
        bl[j] = __ldg((const uint2*)(g_W1l + src));
    }

    for (int kc = 0; kc < 16; kc++) {
        const uint32_t buf = (uint32_t)((kc & 1) * BUF_SZ);

#pragma unroll
        for (int i = 0; i < 4; i++) {
            float4 v = pf[i];
            __nv_bfloat16 hx = __float2bfloat16(v.x), hy = __float2bfloat16(v.y);
            __nv_bfloat16 hz = __float2bfloat16(v.z), hw = __float2bfloat16(v.w);
            *(uint2*)(sm + buf + O_AH + aDst[i]) =
                make_uint2(bfbits(hx) | (bfbits(hy) << 16), bfbits(hz) | (bfbits(hw) << 16));
            __nv_bfloat16 lx = __float2bfloat16(v.x - __bfloat162float(hx));
            __nv_bfloat16 ly = __float2bfloat16(v.y - __bfloat162float(hy));
            __nv_bfloat16 lz = __float2bfloat16(v.z - __bfloat162float(hz));
            __nv_bfloat16 lw = __float2bfloat16(v.w - __bfloat162float(hw));
            *(uint2*)(sm + buf + O_AL + aDst[i]) =
                make_uint2(bfbits(lx) | (bfbits(ly) << 16), bfbits(lz) | (bfbits(lw) << 16));
        }
#pragma unroll
        for (int j = 0; j < 4; j++) {
            int lin = t + j * 256;
            int n = lin >> 4, q = lin & 15;
            uint32_t dst = (uint32_t)(n * (SA_STRIDE * 2) + q * 8);
            *(uint2*)(sm + buf + O_BH + dst) = bh[j];
            *(uint2*)(sm + buf + O_BL + dst) = bl[j];
        }
        __syncthreads();

        if (kc < 15) {
#pragma unroll
            for (int i = 0; i < 4; i++)
                pf[i] = __ldg(xb + rbase[i] + (kc + 1) * 16);
#pragma unroll
            for (int j = 0; j < 4; j++) {
                int lin = t + j * 256;
                int n = lin >> 4, q = lin & 15;
                size_t src = (size_t)n * DF + (kc + 1) * 64 + q * 4;
                bh[j] = __ldg((const uint2*)(g_W1h + src));
                bl[j] = __ldg((const uint2*)(g_W1l + src));
            }
        }

#pragma unroll
        for (int ks = 0; ks < 4; ks++) {
            uint32_t ah[4], al[4];
            LDSM4(ah, buf + aLd + O_AH + ks * 32);
            LDSM4(al, buf + aLd + O_AL + ks * 32);
#pragma unroll
            for (int jp = 0; jp < 2; jp++) {
                uint32_t vh[4], vl[4];
                uint32_t boff = (uint32_t)(jp * (16 * SA_STRIDE * 2) + ks * 32);
                LDSM4(vh, buf + bLd + O_BH + boff);
                LDSM4(vl, buf + bLd + O_BL + boff);
                mma16816(acc[2 * jp],     ah, vh[0], vh[1]);
                mma16816(acc[2 * jp],     ah, vl[0], vl[1]);
                mma16816(acc[2 * jp],     al, vh[0], vh[1]);
                mma16816(acc[2 * jp + 1], ah, vh[2], vh[3]);
                mma16816(acc[2 * jp + 1], ah, vl[2], vl[3]);
                mma16816(acc[2 * jp + 1], al, vh[2], vh[3]);
            }
        }
    }

    // ---- epilogue: fp32 only (mirror built later by k_scale with dinv) ----
    const int g = lane >> 2, tig = lane & 3;
    const int r0 = m0 + strip * 16 + g;
    const int r1 = r0 + 8;
#pragma unroll
    for (int nt = 0; nt < 4; nt++) {
        int c = nhalf * 32 + nt * 8 + tig * 2;
        *(float2*)(g_H1 + (size_t)r0 * 64 + c) = make_float2(acc[nt][0], acc[nt][1]);
        *(float2*)(g_H1 + (size_t)r1 * 64 + c) = make_float2(acc[nt][2], acc[nt][3]);
    }
}

// ---------------- k_scale: H1s = fp16(dinv * H1), after join ----------------
__global__ void k_scale() {
    int idx = blockIdx.x * blockDim.x + threadIdx.x;  // half2 index, NN*32 total
    if (idx >= NN * 32) return;
    int n = idx >> 5;
    float d = __ldg(g_dinv + n);
    float2 v = ((const float2*)g_H1)[idx];
    ((__half2*)g_H1s)[idx] = __floats2half2_rn(v.x * d, v.y * d);
}

// ---------------- gather1 + relu + bias + GEMM2 fused (warp per node) ----------------
// src-only edges (int4 x2 per 8 edges); rows pre-scaled fp16; self fp32.
__global__ void __launch_bounds__(256) k_gather1(const float* __restrict__ b1,
                                                 const float* __restrict__ W2) {
    __shared__ float sW[HID * NC];   // 10240 B
    __shared__ float sO[8][HID];     // 2048 B
    for (int i = threadIdx.x; i < HID * NC; i += 256) sW[i] = __ldg(W2 + i);
    __syncthreads();

    const int w = threadIdx.x >> 5, lane = threadIdx.x & 31;
    const int n = blockIdx.x * 8 + w;

    const int start = __ldg(g_rowptr + n);
    const int cnt   = __ldg(g_deg + n);
    float2 nbv = make_float2(0.f, 0.f);   // Σ H1s[src]
    int i = 0;
    int peel = (4 - (start & 3)) & 3;
    peel = peel < cnt ? peel : cnt;
    for (; i < peel; i++) {
        int s = __ldg(g_src + start + i);
        float2 f = __half22float2(__ldg((const __half2*)(g_H1s + (size_t)s * 64) + lane));
        nbv.x += f.x; nbv.y += f.y;
    }
    const int4* p4 = (const int4*)(g_src + start + i);
    const int nb8 = (cnt - i) >> 3;
    for (int b = 0; b < nb8; b++) {
        int4 q0 = __ldg(p4 + 2 * b), q1 = __ldg(p4 + 2 * b + 1);
        float2 f0 = __half22float2(__ldg((const __half2*)(g_H1s + (size_t)q0.x * 64) + lane));
        float2 f1 = __half22float2(__ldg((const __half2*)(g_H1s + (size_t)q0.y * 64) + lane));
        float2 f2 = __half22float2(__ldg((const __half2*)(g_H1s + (size_t)q0.z * 64) + lane));
        float2 f3 = __half22float2(__ldg((const __half2*)(g_H1s + (size_t)q0.w * 64) + lane));
        float2 f4 = __half22float2(__ldg((const __half2*)(g_H1s + (size_t)q1.x * 64) + lane));
        float2 f5 = __half22float2(__ldg((const __half2*)(g_H1s + (size_t)q1.y * 64) + lane));
        float2 f6 = __half22float2(__ldg((const __half2*)(g_H1s + (size_t)q1.z * 64) + lane));
        float2 f7 = __half22float2(__ldg((const __half2*)(g_H1s + (size_t)q1.w * 64) + lane));
        nbv.x += f0.x + f1.x + f2.x + f3.x + f4.x + f5.x + f6.x + f7.x;
        nbv.y += f0.y + f1.y + f2.y + f3.y + f4.y + f5.y + f6.y + f7.y;
    }
    for (i += nb8 * 8; i < cnt; i++) {
        int s = __ldg(g_src + start + i);
        float2 f = __half22float2(__ldg((const __half2*)(g_H1s + (size_t)s * 64) + lane));
        nbv.x += f.x; nbv.y += f.y;
    }
    float di = __ldg(g_dinv + n);
    float2 self = __ldg((const float2*)(g_H1 + (size_t)n * 64) + lane);
    float2 b = __ldg((const float2*)b1 + lane);
    float ox = fmaxf(di * nbv.x + di * di * self.x + b.x, 0.f);
    float oy = fmaxf(di * nbv.y + di * di * self.y + b.y, 0.f);
    sO[w][lane * 2]     = ox;
    sO[w][lane * 2 + 1] = oy;
    __syncwarp();

    if (lane < 20) {
        float h0 = 0.f, h1 = 0.f;
        const float* o = sO[w];
#pragma unroll
        for (int k = 0; k < HID; k++) {
            float ov = o[k];
            h0 = fmaf(ov, sW[k * NC + 2 * lane],     h0);
            h1 = fmaf(ov, sW[k * NC + 2 * lane + 1], h1);
        }
        *(float2*)(g_H2 + (size_t)n * NC + lane * 2) = make_float2(h0, h1);
        *(__half2*)(g_H2s + (size_t)n * NC + lane * 2) = __floats2half2_rn(h0 * di, h1 * di);
    }
}

// ---------------- gather2 + bias + log_softmax (warp per node) ----------------
__global__ void __launch_bounds__(256) k_gather2(const float* __restrict__ b2,
                                                 float* __restrict__ out) {
    const int w = threadIdx.x >> 5, lane = threadIdx.x & 31;
    const int n = blockIdx.x * 8 + w;
    const bool act = lane < 20;  // 20 lanes x 2 = 40 cols
    const int start = __ldg(g_rowptr + n);
    const int cnt   = __ldg(g_deg + n);
    float2 nbv = make_float2(0.f, 0.f);   // Σ H2s[src]
    int i = 0;
    int peel = (4 - (start & 3)) & 3;
    peel = peel < cnt ? peel : cnt;
    for (; i < peel; i++) {
        int s = __ldg(g_src + start + i);
        if (act) {
            float2 f = __half22float2(__ldg((const __half2*)(g_H2s + (size_t)s * NC) + lane));
            nbv.x += f.x; nbv.y += f.y;
        }
    }
    const int4* p4 = (const int4*)(g_src + start + i);
    const int nb8 = (cnt - i) >> 3;
    for (int b = 0; b < nb8; b++) {
        int4 q0 = __ldg(p4 + 2 * b), q1 = __ldg(p4 + 2 * b + 1);
        if (act) {
            float2 f0 = __half22float2(__ldg((const __half2*)(g_H2s + (size_t)q0.x * NC) + lane));
            float2 f1 = __half22float2(__ldg((const __half2*)(g_H2s + (size_t)q0.y * NC) + lane));
            float2 f2 = __half22float2(__ldg((const __half2*)(g_H2s + (size_t)q0.z * NC) + lane));
            float2 f3 = __half22float2(__ldg((const __half2*)(g_H2s + (size_t)q0.w * NC) + lane));
            float2 f4 = __half22float2(__ldg((const __half2*)(g_H2s + (size_t)q1.x * NC) + lane));
            float2 f5 = __half22float2(__ldg((const __half2*)(g_H2s + (size_t)q1.y * NC) + lane));
            float2 f6 = __half22float2(__ldg((const __half2*)(g_H2s + (size_t)q1.z * NC) + lane));
            float2 f7 = __half22float2(__ldg((const __half2*)(g_H2s + (size_t)q1.w * NC) + lane));
            nbv.x += f0.x + f1.x + f2.x + f3.x + f4.x + f5.x + f6.x + f7.x;
            nbv.y += f0.y + f1.y + f2.y + f3.y + f4.y + f5.y + f6.y + f7.y;
        }
    }
    for (i += nb8 * 8; i < cnt; i++) {
        int s = __ldg(g_src + start + i);
        if (act) {
            float2 f = __half22float2(__ldg((const __half2*)(g_H2s + (size_t)s * NC) + lane));
            nbv.x += f.x; nbv.y += f.y;
        }
    }
    float2 z = make_float2(-CUDART_INF_F, -CUDART_INF_F);
    if (act) {
        float di = __ldg(g_dinv + n);
        float2 self = __ldg((const float2*)(g_H2 + (size_t)n * NC) + lane);
        float2 b = __ldg((const float2*)b2 + lane);
        z.x = di * nbv.x + di * di * self.x + b.x;
        z.y = di * nbv.y + di * di * self.y + b.y;
    }
    float m = fmaxf(z.x, z.y);
#pragma unroll
    for (int off = 16; off; off >>= 1) m = fmaxf(m, __shfl_xor_sync(0xffffffffu, m, off));
    float s = act ? (__expf(z.x - m) + __expf(z.y - m)) : 0.f;
#pragma unroll
    for (int off = 16; off; off >>= 1) s += __shfl_xor_sync(0xffffffffu, s, off);
    float l = m + __logf(s);
    if (act)
        *(float2*)(out + (size_t)n * NC + lane * 2) = make_float2(z.x - l, z.y - l);
}

// ---------------- launch ----------------
extern "C" void kernel_launch(void* const* d_in, const int* in_sizes, int n_in,
                              void* d_out, int out_size) {
    const float* x  = (const float*)d_in[0];
    const int*   ei = (const int*)d_in[1];
    const float* W1 = (const float*)d_in[2];
    const float* b1 = (const float*)d_in[3];
    const float* W2 = (const float*)d_in[4];
    const float* b2 = (const float*)d_in[5];
    const int* row = ei;         // sources
    const int* col = ei + NE;    // targets
    float* out = (float*)d_out;

    static void* deg_ptr = nullptr;
    static cudaStream_t s2 = nullptr;
    static cudaEvent_t evFork = nullptr, evJoin = nullptr;
    if (!deg_ptr) {  // resolved on the (non-captured) correctness call
        cudaFuncSetAttribute(k_gemm1, cudaFuncAttributeMaxDynamicSharedMemorySize, SM_TOTAL);
        cudaGetSymbolAddress(&deg_ptr, g_deg);
        cudaStreamCreateWithFlags(&s2, cudaStreamNonBlocking);
        cudaEventCreateWithFlags(&evFork, cudaEventDisableTiming);
        cudaEventCreateWithFlags(&evJoin, cudaEventDisableTiming);
    }

    // fork: stream B runs wsplit + gemm1 (independent of CSR chain)
    cudaEventRecord(evFork, 0);
    cudaStreamWaitEvent(s2, evFork, 0);
    k_wsplit<<<(DF * HID + 255) / 256, 256, 0, s2>>>(W1);
    k_gemm1<<<NN / 64, 256, SM_TOTAL, s2>>>(x);
    cudaEventRecord(evJoin, s2);

    // default stream: CSR build chain
    cudaMemsetAsync(deg_ptr, 0, NN * sizeof(int));
    k_hist<<<(NE + 255) / 256, 256>>>(col);
    k_scanA<<<SCAN_NB, 256>>>();
    k_scanB<<<1, 256>>>();
    k_scanC<<<SCAN_NB, 256>>>();
    k_fill<<<(NE + 255) / 256, 256>>>(row, col);

    // join, build scaled mirror, then gathers
    cudaStreamWaitEvent(0, evJoin, 0);
    k_scale<<<(NN * 32 + 255) / 256, 256>>>();
    k_gather1<<<NN / 8, 256>>>(b1, W2);
    k_gather2<<<NN / 8, 256>>>(b2, out);
}

// round 15
// speedup vs baseline: 1.4248x; 1.0714x over previous
#include <cuda_runtime.h>
#include <cuda_bf16.h>
#include <cuda_fp16.h>
#include <cstdint>
#include <math_constants.h>

// ---------------- problem constants ----------------
static constexpr int NN  = 40000;     // nodes
static constexpr int NE  = 1280000;   // edges
static constexpr int DF  = 1024;      // input feat
static constexpr int HID = 64;        // hidden
static constexpr int NC  = 40;        // classes

// ---------------- device scratch ----------------
__device__ float  g_H1[(size_t)NN * HID];   // x @ W1 (fp32)
__device__ __half g_H1s[(size_t)NN * HID];  // fp16 dinv-scaled mirror (k_scale)
__device__ float  g_H2[(size_t)NN * NC];    // fp32 layer-2 pre-agg
__device__ __half g_H2s[(size_t)NN * NC];   // fp16 dinv-scaled mirror (gather1)
__device__ float  g_dinv[NN];
__device__ int    g_deg[NN];                // in-degree (no self loop)
__device__ int    g_rowptr[NN];             // CSR start per node
__device__ int    g_cursor[NN];
__device__ int    g_rowtmp[NN];             // inclusive scan, pre-base
__device__ int    g_bsum[160];
__device__ int    g_bbase[160];
__device__ __align__(16) int g_src[NE];     // src index only, grouped by dst
__device__ __nv_bfloat16 g_W1b[(size_t)HID * DF];  // W1^T bf16, [n][k]

// ---------------- helpers ----------------
__device__ __forceinline__ uint32_t smem_to_u32(const void* p) {
    uint32_t a;
    asm("{ .reg .u64 t; cvta.to.shared.u64 t, %1; cvt.u32.u64 %0, t; }" : "=r"(a) : "l"(p));
    return a;
}
__device__ __forceinline__ uint32_t bfbits(__nv_bfloat16 h) {
    return (uint32_t)__bfloat16_as_ushort(h);
}
#define LDSM4(r, addr) \
    asm volatile("ldmatrix.sync.aligned.m8n8.x4.shared.b16 {%0,%1,%2,%3}, [%4];" \
                 : "=r"((r)[0]), "=r"((r)[1]), "=r"((r)[2]), "=r"((r)[3]) : "r"(addr))
__device__ __forceinline__ void mma16816(float* c, const uint32_t* a, uint32_t b0, uint32_t b1) {
    asm volatile(
        "mma.sync.aligned.m16n8k16.row.col.f32.bf16.bf16.f32 "
        "{%0,%1,%2,%3}, {%4,%5,%6,%7}, {%8,%9}, {%0,%1,%2,%3};"
        : "+f"(c[0]), "+f"(c[1]), "+f"(c[2]), "+f"(c[3])
        : "r"(a[0]), "r"(a[1]), "r"(a[2]), "r"(a[3]), "r"(b0), "r"(b1));
}

// ---------------- prep ----------------
__global__ void k_hist(const int* __restrict__ col) {
    int e = blockIdx.x * blockDim.x + threadIdx.x;
    if (e < NE) atomicAdd(&g_deg[col[e]], 1);
}
__global__ void k_wsplit(const float* __restrict__ W1) {
    int idx = blockIdx.x * blockDim.x + threadIdx.x;
    if (idx >= DF * HID) return;
    int k = idx >> 6, n = idx & 63;
    g_W1b[(size_t)n * DF + k] = __float2bfloat16(W1[idx]);
}

// ---------------- CSR build: 3-phase scan + fill ----------------
static constexpr int SCAN_NB = (NN + 255) / 256;  // 157
__global__ void k_scanA() {
    __shared__ int s[256];
    int i = blockIdx.x * 256 + threadIdx.x;
    int v = (i < NN) ? g_deg[i] : 0;
    s[threadIdx.x] = v;
    __syncthreads();
#pragma unroll
    for (int off = 1; off < 256; off <<= 1) {
        int t = (threadIdx.x >= off) ? s[threadIdx.x - off] : 0;
        __syncthreads();
        s[threadIdx.x] += t;
        __syncthreads();
    }
    if (i < NN) g_rowtmp[i] = s[threadIdx.x];
    if (threadIdx.x == 255) g_bsum[blockIdx.x] = s[255];
}
__global__ void k_scanB() {
    __shared__ int s[256];
    int v = (threadIdx.x < SCAN_NB) ? g_bsum[threadIdx.x] : 0;
    s[threadIdx.x] = v;
    __syncthreads();
#pragma unroll
    for (int off = 1; off < 256; off <<= 1) {
        int t = (threadIdx.x >= off) ? s[threadIdx.x - off] : 0;
        __syncthreads();
        s[threadIdx.x] += t;
        __syncthreads();
    }
    if (threadIdx.x < SCAN_NB) g_bbase[threadIdx.x] = s[threadIdx.x] - v;  // exclusive
}
__global__ void k_scanC() {  // rowptr/cursor + dinv fused
    int i = blockIdx.x * 256 + threadIdx.x;
    if (i >= NN) return;
    int d = g_deg[i];
    int start = g_rowtmp[i] + g_bbase[blockIdx.x] - d;
    g_rowptr[i] = start;
    g_cursor[i] = start;
    g_dinv[i] = rsqrtf((float)(d + 1));  // +1 self loop
}
__global__ void k_fill(const int* __restrict__ row, const int* __restrict__ col) {
    int e = blockIdx.x * blockDim.x + threadIdx.x;
    if (e >= NE) return;
    int r = __ldg(row + e), c = __ldg(col + e);
    int p = atomicAdd(&g_cursor[c], 1);
    g_src[p] = r;
}

// ---------------- GEMM1: SINGLE-PASS bf16 mma, M-tile 64, DOUBLE-BUFFERED ----------------
static constexpr int SA_STRIDE = 72;                 // bf16 elems per row (144B)
static constexpr int O_A = 0;
static constexpr int O_B = 64 * SA_STRIDE * 2;       // 9216
static constexpr int BUF_SZ = O_B + 64 * SA_STRIDE * 2;  // 18432
static constexpr int SM_TOTAL = 2 * BUF_SZ;          // 36864

__global__ void __launch_bounds__(256, 2) k_gemm1(const float* __restrict__ x) {
    extern __shared__ char sm[];
    const uint32_t smb = smem_to_u32(sm);
    const int t = threadIdx.x;
    const int lane = t & 31, w = t >> 5;
    const int strip = w >> 1, nhalf = w & 1;
    const int m0 = blockIdx.x * 64;

    const int r0t = t >> 4;
    const int c4  = t & 15;
    const float4* xb = (const float4*)x;
    size_t rbase[4];
    uint32_t aDst[4];
#pragma unroll
    for (int i = 0; i < 4; i++) {
        int rowg = m0 + r0t + 16 * i;
        rbase[i] = (size_t)rowg * 256 + c4;  // float4 units
        aDst[i] = (uint32_t)((r0t + 16 * i) * (SA_STRIDE * 2) + c4 * 8);
    }
    const uint32_t aLd = smb +
        (uint32_t)((strip * 16 + (lane & 7) + ((lane >> 3) & 1) * 8) * (SA_STRIDE * 2) +
                   (lane >> 4) * 16);
    const uint32_t bLd = smb +
        (uint32_t)((nhalf * 32 + ((lane >> 4) * 8) + (lane & 7)) * (SA_STRIDE * 2) +
                   ((lane >> 3) & 1) * 16);

    float acc[4][4];
#pragma unroll
    for (int j = 0; j < 4; j++)
#pragma unroll
        for (int q = 0; q < 4; q++) acc[j][q] = 0.f;

    // prologue: chunk-0 operands into registers
    float4 pf[4];
    uint2 bh[4];
#pragma unroll
    for (int i = 0; i < 4; i++) pf[i] = __ldg(xb + rbase[i]);
#pragma unroll
    for (int j = 0; j < 4; j++) {
        int lin = t + j * 256;
        int n = lin >> 4, q = lin & 15;
        bh[j] = __ldg((const uint2*)(g_W1b + (size_t)n * DF + q * 4));
    }

    for (int kc = 0; kc < 16; kc++) {
        const uint32_t buf = (uint32_t)((kc & 1) * BUF_SZ);

        // ---- convert & store A chunk kc ----
#pragma unroll
        for (int i = 0; i < 4; i++) {
            float4 v = pf[i];
            __nv_bfloat16 hx = __float2bfloat16(v.x), hy = __float2bfloat16(v.y);
            __nv_bfloat16 hz = __float2bfloat16(v.z), hw = __float2bfloat16(v.w);
            *(uint2*)(sm + buf + O_A + aDst[i]) =
                make_uint2(bfbits(hx) | (bfbits(hy) << 16), bfbits(hz) | (bfbits(hw) << 16));
        }
        // ---- store B chunk kc ----
#pragma unroll
        for (int j = 0; j < 4; j++) {
            int lin = t + j * 256;
            int n = lin >> 4, q = lin & 15;
            *(uint2*)(sm + buf + O_B + (uint32_t)(n * (SA_STRIDE * 2) + q * 8)) = bh[j];
        }
        __syncthreads();

        // ---- issue chunk kc+1 global loads (latency hides under MMA) ----
        if (kc < 15) {
#pragma unroll
            for (int i = 0; i < 4; i++)
                pf[i] = __ldg(xb + rbase[i] + (kc + 1) * 16);
#pragma unroll
            for (int j = 0; j < 4; j++) {
                int lin = t + j * 256;
                int n = lin >> 4, q = lin & 15;
                bh[j] = __ldg((const uint2*)(g_W1b + (size_t)n * DF + (kc + 1) * 64 + q * 4));
            }
        }

        // ---- MMA on chunk kc: 4 k16 steps x 2 jp (16 n each), single pass ----
#pragma unroll
        for (int ks = 0; ks < 4; ks++) {
            uint32_t ah[4];
            LDSM4(ah, buf + aLd + O_A + ks * 32);
#pragma unroll
            for (int jp = 0; jp < 2; jp++) {
                uint32_t vh[4];
                LDSM4(vh, buf + bLd + O_B + (uint32_t)(jp * (16 * SA_STRIDE * 2) + ks * 32));
                mma16816(acc[2 * jp],     ah, vh[0], vh[1]);
                mma16816(acc[2 * jp + 1], ah, vh[2], vh[3]);
            }
        }
        // no second barrier: next iteration writes the OTHER buffer
    }

    // ---- epilogue: fp32 only (mirror built later by k_scale with dinv) ----
    const int g = lane >> 2, tig = lane & 3;
    const int r0 = m0 + strip * 16 + g;
    const int r1 = r0 + 8;
#pragma unroll
    for (int nt = 0; nt < 4; nt++) {
        int c = nhalf * 32 + nt * 8 + tig * 2;
        *(float2*)(g_H1 + (size_t)r0 * 64 + c) = make_float2(acc[nt][0], acc[nt][1]);
        *(float2*)(g_H1 + (size_t)r1 * 64 + c) = make_float2(acc[nt][2], acc[nt][3]);
    }
}

// ---------------- k_scale: H1s = fp16(dinv * H1), after join ----------------
__global__ void k_scale() {
    int idx = blockIdx.x * blockDim.x + threadIdx.x;  // half2 index, NN*32 total
    if (idx >= NN * 32) return;
    int n = idx >> 5;
    float d = __ldg(g_dinv + n);
    float2 v = ((const float2*)g_H1)[idx];
    ((__half2*)g_H1s)[idx] = __floats2half2_rn(v.x * d, v.y * d);
}

// ---------------- gather1 + relu + bias + GEMM2 fused (warp per node) ----------------
// src-only edges (int4 x2 per 8 edges); rows pre-scaled fp16; self fp32.
__global__ void __launch_bounds__(256) k_gather1(const float* __restrict__ b1,
                                                 const float* __restrict__ W2) {
    __shared__ float sW[HID * NC];   // 10240 B
    __shared__ float sO[8][HID];     // 2048 B
    for (int i = threadIdx.x; i < HID * NC; i += 256) sW[i] = __ldg(W2 + i);
    __syncthreads();

    const int w = threadIdx.x >> 5, lane = threadIdx.x & 31;
    const int n = blockIdx.x * 8 + w;

    const int start = __ldg(g_rowptr + n);
    const int cnt   = __ldg(g_deg + n);
    float2 nbv = make_float2(0.f, 0.f);   // Σ H1s[src]
    int i = 0;
    int peel = (4 - (start & 3)) & 3;
    peel = peel < cnt ? peel : cnt;
    for (; i < peel; i++) {
        int s = __ldg(g_src + start + i);
        float2 f = __half22float2(__ldg((const __half2*)(g_H1s + (size_t)s * 64) + lane));
        nbv.x += f.x; nbv.y += f.y;
    }
    const int4* p4 = (const int4*)(g_src + start + i);
    const int nb8 = (cnt - i) >> 3;
    for (int b = 0; b < nb8; b++) {
        int4 q0 = __ldg(p4 + 2 * b), q1 = __ldg(p4 + 2 * b + 1);
        float2 f0 = __half22float2(__ldg((const __half2*)(g_H1s + (size_t)q0.x * 64) + lane));
        float2 f1 = __half22float2(__ldg((const __half2*)(g_H1s + (size_t)q0.y * 64) + lane));
        float2 f2 = __half22float2(__ldg((const __half2*)(g_H1s + (size_t)q0.z * 64) + lane));
        float2 f3 = __half22float2(__ldg((const __half2*)(g_H1s + (size_t)q0.w * 64) + lane));
        float2 f4 = __half22float2(__ldg((const __half2*)(g_H1s + (size_t)q1.x * 64) + lane));
        float2 f5 = __half22float2(__ldg((const __half2*)(g_H1s + (size_t)q1.y * 64) + lane));
        float2 f6 = __half22float2(__ldg((const __half2*)(g_H1s + (size_t)q1.z * 64) + lane));
        float2 f7 = __half22float2(__ldg((const __half2*)(g_H1s + (size_t)q1.w * 64) + lane));
        nbv.x += f0.x + f1.x + f2.x + f3.x + f4.x + f5.x + f6.x + f7.x;
        nbv.y += f0.y + f1.y + f2.y + f3.y + f4.y + f5.y + f6.y + f7.y;
    }
    for (i += nb8 * 8; i < cnt; i++) {
        int s = __ldg(g_src + start + i);
        float2 f = __half22float2(__ldg((const __half2*)(g_H1s + (size_t)s * 64) + lane));
        nbv.x += f.x; nbv.y += f.y;
    }
    float di = __ldg(g_dinv + n);
    float2 self = __ldg((const float2*)(g_H1 + (size_t)n * 64) + lane);
    float2 b = __ldg((const float2*)b1 + lane);
    float ox = fmaxf(di * nbv.x + di * di * self.x + b.x, 0.f);
    float oy = fmaxf(di * nbv.y + di * di * self.y + b.y, 0.f);
    sO[w][lane * 2]     = ox;
    sO[w][lane * 2 + 1] = oy;
    __syncwarp();

    if (lane < 20) {
        float h0 = 0.f, h1 = 0.f;
        const float* o = sO[w];
#pragma unroll
        for (int k = 0; k < HID; k++) {
            float ov = o[k];
            h0 = fmaf(ov, sW[k * NC + 2 * lane],     h0);
            h1 = fmaf(ov, sW[k * NC + 2 * lane + 1], h1);
        }
        *(float2*)(g_H2 + (size_t)n * NC + lane * 2) = make_float2(h0, h1);
        *(__half2*)(g_H2s + (size_t)n * NC + lane * 2) = __floats2half2_rn(h0 * di, h1 * di);
    }
}

// ---------------- gather2 + bias + log_softmax (warp per node) ----------------
__global__ void __launch_bounds__(256) k_gather2(const float* __restrict__ b2,
                                                 float* __restrict__ out) {
    const int w = threadIdx.x >> 5, lane = threadIdx.x & 31;
    const int n = blockIdx.x * 8 + w;
    const bool act = lane < 20;  // 20 lanes x 2 = 40 cols
    const int start = __ldg(g_rowptr + n);
    const int cnt   = __ldg(g_deg + n);
    float2 nbv = make_float2(0.f, 0.f);   // Σ H2s[src]
    int i = 0;
    int peel = (4 - (start & 3)) & 3;
    peel = peel < cnt ? peel : cnt;
    for (; i < peel; i++) {
        int s = __ldg(g_src + start + i);
        if (act) {
            float2 f = __half22float2(__ldg((const __half2*)(g_H2s + (size_t)s * NC) + lane));
            nbv.x += f.x; nbv.y += f.y;
        }
    }
    const int4* p4 = (const int4*)(g_src + start + i);
    const int nb8 = (cnt - i) >> 3;
    for (int b = 0; b < nb8; b++) {
        int4 q0 = __ldg(p4 + 2 * b), q1 = __ldg(p4 + 2 * b + 1);
        if (act) {
            float2 f0 = __half22float2(__ldg((const __half2*)(g_H2s + (size_t)q0.x * NC) + lane));
            float2 f1 = __half22float2(__ldg((const __half2*)(g_H2s + (size_t)q0.y * NC) + lane));
            float2 f2 = __half22float2(__ldg((const __half2*)(g_H2s + (size_t)q0.z * NC) + lane));
            float2 f3 = __half22float2(__ldg((const __half2*)(g_H2s + (size_t)q0.w * NC) + lane));
            float2 f4 = __half22float2(__ldg((const __half2*)(g_H2s + (size_t)q1.x * NC) + lane));
            float2 f5 = __half22float2(__ldg((const __half2*)(g_H2s + (size_t)q1.y * NC) + lane));
            float2 f6 = __half22float2(__ldg((const __half2*)(g_H2s + (size_t)q1.z * NC) + lane));
            float2 f7 = __half22float2(__ldg((const __half2*)(g_H2s + (size_t)q1.w * NC) + lane));
            nbv.x += f0.x + f1.x + f2.x + f3.x + f4.x + f5.x + f6.x + f7.x;
            nbv.y += f0.y + f1.y + f2.y + f3.y + f4.y + f5.y + f6.y + f7.y;
        }
    }
    for (i += nb8 * 8; i < cnt; i++) {
        int s = __ldg(g_src + start + i);
        if (act) {
            float2 f = __half22float2(__ldg((const __half2*)(g_H2s + (size_t)s * NC) + lane));
            nbv.x += f.x; nbv.y += f.y;
        }
    }
    float2 z = make_float2(-CUDART_INF_F, -CUDART_INF_F);
    if (act) {
        float di = __ldg(g_dinv + n);
        float2 self = __ldg((const float2*)(g_H2 + (size_t)n * NC) + lane);
        float2 b = __ldg((const float2*)b2 + lane);
        z.x = di * nbv.x + di * di * self.x + b.x;
        z.y = di * nbv.y + di * di * self.y + b.y;
    }
    float m = fmaxf(z.x, z.y);
#pragma unroll
    for (int off = 16; off; off >>= 1) m = fmaxf(m, __shfl_xor_sync(0xffffffffu, m, off));
    float s = act ? (__expf(z.x - m) + __expf(z.y - m)) : 0.f;
#pragma unroll
    for (int off = 16; off; off >>= 1) s += __shfl_xor_sync(0xffffffffu, s, off);
    float l = m + __logf(s);
    if (act)
        *(float2*)(out + (size_t)n * NC + lane * 2) = make_float2(z.x - l, z.y - l);
}

// ---------------- launch ----------------
extern "C" void kernel_launch(void* const* d_in, const int* in_sizes, int n_in,
                              void* d_out, int out_size) {
    const float* x  = (const float*)d_in[0];
    const int*   ei = (const int*)d_in[1];
    const float* W1 = (const float*)d_in[2];
    const float* b1 = (const float*)d_in[3];
    const float* W2 = (const float*)d_in[4];
    const float* b2 = (const float*)d_in[5];
    const int* row = ei;         // sources
    const int* col = ei + NE;    // targets
    float* out = (float*)d_out;

    static void* deg_ptr = nullptr;
    static cudaStream_t s2 = nullptr;
    static cudaEvent_t evFork = nullptr, evJoin = nullptr;
    if (!deg_ptr) {  // resolved on the (non-captured) correctness call
        cudaFuncSetAttribute(k_gemm1, cudaFuncAttributeMaxDynamicSharedMemorySize, SM_TOTAL);
        cudaGetSymbolAddress(&deg_ptr, g_deg);
        cudaStreamCreateWithFlags(&s2, cudaStreamNonBlocking);
        cudaEventCreateWithFlags(&evFork, cudaEventDisableTiming);
        cudaEventCreateWithFlags(&evJoin, cudaEventDisableTiming);
    }

    // fork: stream B runs wsplit + single-pass gemm1 (independent of CSR chain)
    cudaEventRecord(evFork, 0);
    cudaStreamWaitEvent(s2, evFork, 0);
    k_wsplit<<<(DF * HID + 255) / 256, 256, 0, s2>>>(W1);
    k_gemm1<<<NN / 64, 256, SM_TOTAL, s2>>>(x);
    cudaEventRecord(evJoin, s2);

    // default stream: CSR build chain
    cudaMemsetAsync(deg_ptr, 0, NN * sizeof(int));
    k_hist<<<(NE + 255) / 256, 256>>>(col);
    k_scanA<<<SCAN_NB, 256>>>();
    k_scanB<<<1, 256>>>();
    k_scanC<<<SCAN_NB, 256>>>();
    k_fill<<<(NE + 255) / 256, 256>>>(row, col);

    // join, build scaled mirror, then gathers
    cudaStreamWaitEvent(0, evJoin, 0);
    k_scale<<<(NN * 32 + 255) / 256, 256>>>();
    k_gather1<<<NN / 8, 256>>>(b1, W2);
    k_gather2<<<NN / 8, 256>>>(b2, out);
}

// round 17
// speedup vs baseline: 1.4433x; 1.0129x over previous
#include <cuda_runtime.h>
#include <cuda_bf16.h>
#include <cuda_fp16.h>
#include <cstdint>
#include <math_constants.h>

// ---------------- problem constants ----------------
static constexpr int NN  = 40000;     // nodes
static constexpr int NE  = 1280000;   // edges
static constexpr int DF  = 1024;      // input feat
static constexpr int HID = 64;        // hidden
static constexpr int NC  = 40;        // classes

// ---------------- device scratch ----------------
__device__ float  g_H1[(size_t)NN * HID];   // x @ W1 (fp32)
__device__ __half g_H1s[(size_t)NN * HID];  // fp16 dinv-scaled mirror (k_scale)
__device__ float  g_H2[(size_t)NN * NC];    // fp32 layer-2 pre-agg
__device__ __half g_H2s[(size_t)NN * NC];   // fp16 dinv-scaled mirror (gather1)
__device__ float  g_dinv[NN];
__device__ int    g_deg[NN];                // in-degree (no self loop)
__device__ int    g_rowptr[NN];             // CSR start per node
__device__ int    g_cursor[NN];
__device__ int    g_rowtmp[NN];             // inclusive scan, pre-base
__device__ int    g_bsum[160];
__device__ int    g_bbase[160];
__device__ __align__(16) int g_src[NE];     // src index only, grouped by dst
__device__ __nv_bfloat16 g_W1b[(size_t)HID * DF];  // W1^T bf16, [n][k]

// ---------------- helpers ----------------
__device__ __forceinline__ uint32_t smem_to_u32(const void* p) {
    uint32_t a;
    asm("{ .reg .u64 t; cvta.to.shared.u64 t, %1; cvt.u32.u64 %0, t; }" : "=r"(a) : "l"(p));
    return a;
}
__device__ __forceinline__ uint32_t bfbits(__nv_bfloat16 h) {
    return (uint32_t)__bfloat16_as_ushort(h);
}
#define LDSM4(r, addr) \
    asm volatile("ldmatrix.sync.aligned.m8n8.x4.shared.b16 {%0,%1,%2,%3}, [%4];" \
                 : "=r"((r)[0]), "=r"((r)[1]), "=r"((r)[2]), "=r"((r)[3]) : "r"(addr))
__device__ __forceinline__ void mma16816(float* c, const uint32_t* a, uint32_t b0, uint32_t b1) {
    asm volatile(
        "mma.sync.aligned.m16n8k16.row.col.f32.bf16.bf16.f32 "
        "{%0,%1,%2,%3}, {%4,%5,%6,%7}, {%8,%9}, {%0,%1,%2,%3};"
        : "+f"(c[0]), "+f"(c[1]), "+f"(c[2]), "+f"(c[3])
        : "r"(a[0]), "r"(a[1]), "r"(a[2]), "r"(a[3]), "r"(b0), "r"(b1));
}
// unpack 8 fp16 (uint4) and add into acc[8]
__device__ __forceinline__ void acc_h8(float* acc, uint4 r) {
    float2 f0 = __half22float2(*reinterpret_cast<__half2*>(&r.x));
    float2 f1 = __half22float2(*reinterpret_cast<__half2*>(&r.y));
    float2 f2 = __half22float2(*reinterpret_cast<__half2*>(&r.z));
    float2 f3 = __half22float2(*reinterpret_cast<__half2*>(&r.w));
    acc[0] += f0.x; acc[1] += f0.y; acc[2] += f1.x; acc[3] += f1.y;
    acc[4] += f2.x; acc[5] += f2.y; acc[6] += f3.x; acc[7] += f3.y;
}

// ---------------- prep ----------------
__global__ void k_hist(const int* __restrict__ col) {
    int e = blockIdx.x * blockDim.x + threadIdx.x;
    if (e < NE) atomicAdd(&g_deg[col[e]], 1);
}
__global__ void k_wsplit(const float* __restrict__ W1) {
    int idx = blockIdx.x * blockDim.x + threadIdx.x;
    if (idx >= DF * HID) return;
    int k = idx >> 6, n = idx & 63;
    g_W1b[(size_t)n * DF + k] = __float2bfloat16(W1[idx]);
}

// ---------------- CSR build: 3-phase scan + fill ----------------
static constexpr int SCAN_NB = (NN + 255) / 256;  // 157
__global__ void k_scanA() {
    __shared__ int s[256];
    int i = blockIdx.x * 256 + threadIdx.x;
    int v = (i < NN) ? g_deg[i] : 0;
    s[threadIdx.x] = v;
    __syncthreads();
#pragma unroll
    for (int off = 1; off < 256; off <<= 1) {
        int t = (threadIdx.x >= off) ? s[threadIdx.x - off] : 0;
        __syncthreads();
        s[threadIdx.x] += t;
        __syncthreads();
    }
    if (i < NN) g_rowtmp[i] = s[threadIdx.x];
    if (threadIdx.x == 255) g_bsum[blockIdx.x] = s[255];
}
__global__ void k_scanB() {
    __shared__ int s[256];
    int v = (threadIdx.x < SCAN_NB) ? g_bsum[threadIdx.x] : 0;
    s[threadIdx.x] = v;
    __syncthreads();
#pragma unroll
    for (int off = 1; off < 256; off <<= 1) {
        int t = (threadIdx.x >= off) ? s[threadIdx.x - off] : 0;
        __syncthreads();
        s[threadIdx.x] += t;
        __syncthreads();
    }
    if (threadIdx.x < SCAN_NB) g_bbase[threadIdx.x] = s[threadIdx.x] - v;  // exclusive
}
__global__ void k_scanC() {  // rowptr/cursor + dinv fused
    int i = blockIdx.x * 256 + threadIdx.x;
    if (i >= NN) return;
    int d = g_deg[i];
    int start = g_rowtmp[i] + g_bbase[blockIdx.x] - d;
    g_rowptr[i] = start;
    g_cursor[i] = start;
    g_dinv[i] = rsqrtf((float)(d + 1));  // +1 self loop
}
__global__ void k_fill(const int* __restrict__ row, const int* __restrict__ col) {
    int e = blockIdx.x * blockDim.x + threadIdx.x;
    if (e >= NE) return;
    int r = __ldg(row + e), c = __ldg(col + e);
    int p = atomicAdd(&g_cursor[c], 1);
    g_src[p] = r;
}

// ---------------- GEMM1: SINGLE-PASS bf16 mma, M-tile 64, DOUBLE-BUFFERED ----------------
static constexpr int SA_STRIDE = 72;                 // bf16 elems per row (144B)
static constexpr int O_A = 0;
static constexpr int O_B = 64 * SA_STRIDE * 2;       // 9216
static constexpr int BUF_SZ = O_B + 64 * SA_STRIDE * 2;  // 18432
static constexpr int SM_TOTAL = 2 * BUF_SZ;          // 36864

__global__ void __launch_bounds__(256, 2) k_gemm1(const float* __restrict__ x) {
    extern __shared__ char sm[];
    const uint32_t smb = smem_to_u32(sm);
    const int t = threadIdx.x;
    const int lane = t & 31, w = t >> 5;
    const int strip = w >> 1, nhalf = w & 1;
    const int m0 = blockIdx.x * 64;

    const int r0t = t >> 4;
    const int c4  = t & 15;
    const float4* xb = (const float4*)x;
    size_t rbase[4];
    uint32_t aDst[4];
#pragma unroll
    for (int i = 0; i < 4; i++) {
        int rowg = m0 + r0t + 16 * i;
        rbase[i] = (size_t)rowg * 256 + c4;  // float4 units
        aDst[i] = (uint32_t)((r0t + 16 * i) * (SA_STRIDE * 2) + c4 * 8);
    }
    const uint32_t aLd = smb +
        (uint32_t)((strip * 16 + (lane & 7) + ((lane >> 3) & 1) * 8) * (SA_STRIDE * 2) +
                   (lane >> 4) * 16);
    const uint32_t bLd = smb +
        (uint32_t)((nhalf * 32 + ((lane >> 4) * 8) + (lane & 7)) * (SA_STRIDE * 2) +
                   ((lane >> 3) & 1) * 16);

    float acc[4][4];
#pragma unroll
    for (int j = 0; j < 4; j++)
#pragma unroll
        for (int q = 0; q < 4; q++) acc[j][q] = 0.f;

    float4 pf[4];
    uint2 bh[4];
#pragma unroll
    for (int i = 0; i < 4; i++) pf[i] = __ldg(xb + rbase[i]);
#pragma unroll
    for (int j = 0; j < 4; j++) {
        int lin = t + j * 256;
        int n = lin >> 4, q = lin & 15;
        bh[j] = __ldg((const uint2*)(g_W1b + (size_t)n * DF + q * 4));
    }

    for (int kc = 0; kc < 16; kc++) {
        const uint32_t buf = (uint32_t)((kc & 1) * BUF_SZ);

#pragma unroll
        for (int i = 0; i < 4; i++) {
            float4 v = pf[i];
            __nv_bfloat16 hx = __float2bfloat16(v.x), hy = __float2bfloat16(v.y);
            __nv_bfloat16 hz = __float2bfloat16(v.z), hw = __float2bfloat16(v.w);
            *(uint2*)(sm + buf + O_A + aDst[i]) =
                make_uint2(bfbits(hx) | (bfbits(hy) << 16), bfbits(hz) | (bfbits(hw) << 16));
        }
#pragma unroll
        for (int j = 0; j < 4; j++) {
            int lin = t + j * 256;
            int n = lin >> 4, q = lin & 15;
            *(uint2*)(sm + buf + O_B + (uint32_t)(n * (SA_STRIDE * 2) + q * 8)) = bh[j];
        }
        __syncthreads();

        if (kc < 15) {
#pragma unroll
            for (int i = 0; i < 4; i++)
                pf[i] = __ldg(xb + rbase[i] + (kc + 1) * 16);
#pragma unroll
            for (int j = 0; j < 4; j++) {
                int lin = t + j * 256;
                int n = lin >> 4, q = lin & 15;
                bh[j] = __ldg((const uint2*)(g_W1b + (size_t)n * DF + (kc + 1) * 64 + q * 4));
            }
        }

#pragma unroll
        for (int ks = 0; ks < 4; ks++) {
            uint32_t ah[4];
            LDSM4(ah, buf + aLd + O_A + ks * 32);
#pragma unroll
            for (int jp = 0; jp < 2; jp++) {
                uint32_t vh[4];
                LDSM4(vh, buf + bLd + O_B + (uint32_t)(jp * (16 * SA_STRIDE * 2) + ks * 32));
                mma16816(acc[2 * jp],     ah, vh[0], vh[1]);
                mma16816(acc[2 * jp + 1], ah, vh[2], vh[3]);
            }
        }
    }

    const int g = lane >> 2, tig = lane & 3;
    const int r0 = m0 + strip * 16 + g;
    const int r1 = r0 + 8;
#pragma unroll
    for (int nt = 0; nt < 4; nt++) {
        int c = nhalf * 32 + nt * 8 + tig * 2;
        *(float2*)(g_H1 + (size_t)r0 * 64 + c) = make_float2(acc[nt][0], acc[nt][1]);
        *(float2*)(g_H1 + (size_t)r1 * 64 + c) = make_float2(acc[nt][2], acc[nt][3]);
    }
}

// ---------------- k_scale: H1s = fp16(dinv * H1) — runs on s2 overlapped with fill ----------------
__global__ void k_scale() {
    int idx = blockIdx.x * blockDim.x + threadIdx.x;  // half2 index, NN*32 total
    if (idx >= NN * 32) return;
    int n = idx >> 5;
    float d = __ldg(g_dinv + n);
    float2 v = ((const float2*)g_H1)[idx];
    ((__half2*)g_H1s)[idx] = __floats2half2_rn(v.x * d, v.y * d);
}

// ---------------- gather1: 4 groups x 8 lanes, uint4 row loads + GEMM2 fused ----------------
__global__ void __launch_bounds__(256) k_gather1(const float* __restrict__ b1,
                                                 const float* __restrict__ W2) {
    __shared__ float sW[HID * NC];   // 10240 B
    __shared__ float sO[8][HID];     // 2048 B
    for (int i = threadIdx.x; i < HID * NC; i += 256) sW[i] = __ldg(W2 + i);
    __syncthreads();

    const int w = threadIdx.x >> 5, lane = threadIdx.x & 31;
    const int g = lane >> 3, s = lane & 7;
    const int n = blockIdx.x * 8 + w;

    const int start = __ldg(g_rowptr + n);
    const int cnt   = __ldg(g_deg + n);
    float acc[8];
#pragma unroll
    for (int j = 0; j < 8; j++) acc[j] = 0.f;

    int i = 0;
    for (; i + 8 <= cnt; i += 8) {
        int s0 = __ldg(g_src + start + i + g);
        int s1 = __ldg(g_src + start + i + 4 + g);
        uint4 r0 = __ldg((const uint4*)(g_H1s + (size_t)s0 * 64) + s);
        uint4 r1 = __ldg((const uint4*)(g_H1s + (size_t)s1 * 64) + s);
        acc_h8(acc, r0);
        acc_h8(acc, r1);
    }
    for (; i + 4 <= cnt; i += 4) {
        int s0 = __ldg(g_src + start + i + g);
        uint4 r0 = __ldg((const uint4*)(g_H1s + (size_t)s0 * 64) + s);
        acc_h8(acc, r0);
    }
    const int i0 = i;
    for (; i < cnt; i++) {
        int sidx = __ldg(g_src + start + i);
        if (g == i - i0) {
            uint4 r = __ldg((const uint4*)(g_H1s + (size_t)sidx * 64) + s);
            acc_h8(acc, r);
        }
    }
    // combine the 4 groups (lanes with same s)
#pragma unroll
    for (int j = 0; j < 8; j++) {
        acc[j] += __shfl_xor_sync(0xffffffffu, acc[j], 8);
        acc[j] += __shfl_xor_sync(0xffffffffu, acc[j], 16);
    }

    float di = __ldg(g_dinv + n);
    if (lane < 8) {  // group 0 writes sO: lane s owns cols 8s..8s+7
        const float4* sf = (const float4*)(g_H1 + (size_t)n * 64) + 2 * s;
        float4 sf0 = __ldg(sf), sf1 = __ldg(sf + 1);
        float4 bb0 = __ldg((const float4*)b1 + 2 * s);
        float4 bb1 = __ldg((const float4*)b1 + 2 * s + 1);
        float* o = &sO[w][s * 8];
        float dd = di * di;
        o[0] = fmaxf(di * acc[0] + dd * sf0.x + bb0.x, 0.f);
        o[1] = fmaxf(di * acc[1] + dd * sf0.y + bb0.y, 0.f);
        o[2] = fmaxf(di * acc[2] + dd * sf0.z + bb0.z, 0.f);
        o[3] = fmaxf(di * acc[3] + dd * sf0.w + bb0.w, 0.f);
        o[4] = fmaxf(di * acc[4] + dd * sf1.x + bb1.x, 0.f);
        o[5] = fmaxf(di * acc[5] + dd * sf1.y + bb1.y, 0.f);
        o[6] = fmaxf(di * acc[6] + dd * sf1.z + bb1.z, 0.f);
        o[7] = fmaxf(di * acc[7] + dd * sf1.w + bb1.w, 0.f);
    }
    __syncwarp();

    if (lane < 20) {  // fused GEMM2: 2 classes per lane (distinct cols per lane)
        float h0 = 0.f, h1 = 0.f;
        const float* o = sO[w];
#pragma unroll
        for (int k = 0; k < HID; k++) {
            float ov = o[k];
            h0 = fmaf(ov, sW[k * NC + 2 * lane],     h0);
            h1 = fmaf(ov, sW[k * NC + 2 * lane + 1], h1);
        }
        *(float2*)(g_H2 + (size_t)n * NC + lane * 2) = make_float2(h0, h1);
        *(__half2*)(g_H2s + (size_t)n * NC + lane * 2) = __floats2half2_rn(h0 * di, h1 * di);
    }
}

// ---------------- gather2: 4 groups x 8 lanes (5 active), + log_softmax ----------------
__global__ void __launch_bounds__(256) k_gather2(const float* __restrict__ b2,
                                                 float* __restrict__ out) {
    const int w = threadIdx.x >> 5, lane = threadIdx.x & 31;
    const int g = lane >> 3, s = lane & 7;
    const bool act = s < 5;  // 5 x 8 fp16 = 40 cols (row = 80 B = 5 x 16 B exactly)
    const int n = blockIdx.x * 8 + w;

    const int start = __ldg(g_rowptr + n);
    const int cnt   = __ldg(g_deg + n);
    float acc[8];
#pragma unroll
    for (int j = 0; j < 8; j++) acc[j] = 0.f;

    int i = 0;
    for (; i + 8 <= cnt; i += 8) {
        int s0 = __ldg(g_src + start + i + g);
        int s1 = __ldg(g_src + start + i + 4 + g);
        if (act) {
            uint4 r0 = __ldg((const uint4*)(g_H2s + (size_t)s0 * NC) + s);
            uint4 r1 = __ldg((const uint4*)(g_H2s + (size_t)s1 * NC) + s);
            acc_h8(acc, r0);
            acc_h8(acc, r1);
        }
    }
    for (; i + 4 <= cnt; i += 4) {
        int s0 = __ldg(g_src + start + i + g);
        if (act) {
            uint4 r0 = __ldg((const uint4*)(g_H2s + (size_t)s0 * NC) + s);
            acc_h8(acc, r0);
        }
    }
    const int i0 = i;
    for (; i < cnt; i++) {
        int sidx = __ldg(g_src + start + i);
        if (act && g == i - i0) {
            uint4 r = __ldg((const uint4*)(g_H2s + (size_t)sidx * NC) + s);
            acc_h8(acc, r);
        }
    }
#pragma unroll
    for (int j = 0; j < 8; j++) {
        acc[j] += __shfl_xor_sync(0xffffffffu, acc[j], 8);
        acc[j] += __shfl_xor_sync(0xffffffffu, acc[j], 16);
    }

    float z[8];
    float m = -CUDART_INF_F;
    if (act) {
        float di = __ldg(g_dinv + n);
        float dd = di * di;
        const float4* sf = (const float4*)(g_H2 + (size_t)n * NC) + 2 * s;
        float4 sf0 = __ldg(sf), sf1 = __ldg(sf + 1);
        float4 bb0 = __ldg((const float4*)b2 + 2 * s);
        float4 bb1 = __ldg((const float4*)b2 + 2 * s + 1);
        z[0] = di * acc[0] + dd * sf0.x + bb0.x;
        z[1] = di * acc[1] + dd * sf0.y + bb0.y;
        z[2] = di * acc[2] + dd * sf0.z + bb0.z;
        z[3] = di * acc[3] + dd * sf0.w + bb0.w;
        z[4] = di * acc[4] + dd * sf1.x + bb1.x;
        z[5] = di * acc[5] + dd * sf1.y + bb1.y;
        z[6] = di * acc[6] + dd * sf1.z + bb1.z;
        z[7] = di * acc[7] + dd * sf1.w + bb1.w;
#pragma unroll
        for (int j = 0; j < 8; j++) m = fmaxf(m, z[j]);
    }
#pragma unroll
    for (int off = 16; off; off >>= 1) m = fmaxf(m, __shfl_xor_sync(0xffffffffu, m, off));
    // FIX: all 4 groups hold identical z after the combine — only group 0 may
    // contribute to the warp-wide sum, else ssum is counted 4x (log4 shift).
    float ssum = 0.f;
    if (act && g == 0) {
#pragma unroll
        for (int j = 0; j < 8; j++) ssum += __expf(z[j] - m);
    }
#pragma unroll
    for (int off = 16; off; off >>= 1) ssum += __shfl_xor_sync(0xffffffffu, ssum, off);
    float l = m + __logf(ssum);
    if (act && g == 0) {
        float* op = out + (size_t)n * NC + s * 8;
        *(float4*)op       = make_float4(z[0] - l, z[1] - l, z[2] - l, z[3] - l);
        *((float4*)op + 1) = make_float4(z[4] - l, z[5] - l, z[6] - l, z[7] - l);
    }
}

// ---------------- launch ----------------
extern "C" void kernel_launch(void* const* d_in, const int* in_sizes, int n_in,
                              void* d_out, int out_size) {
    const float* x  = (const float*)d_in[0];
    const int*   ei = (const int*)d_in[1];
    const float* W1 = (const float*)d_in[2];
    const float* b1 = (const float*)d_in[3];
    const float* W2 = (const float*)d_in[4];
    const float* b2 = (const float*)d_in[5];
    const int* row = ei;         // sources
    const int* col = ei + NE;    // targets
    float* out = (float*)d_out;

    static void* deg_ptr = nullptr;
    static cudaStream_t s2 = nullptr;
    static cudaEvent_t evFork = nullptr, evC = nullptr, evJoin = nullptr;
    if (!deg_ptr) {  // resolved on the (non-captured) correctness call
        cudaFuncSetAttribute(k_gemm1, cudaFuncAttributeMaxDynamicSharedMemorySize, SM_TOTAL);
        cudaGetSymbolAddress(&deg_ptr, g_deg);
        cudaStreamCreateWithFlags(&s2, cudaStreamNonBlocking);
        cudaEventCreateWithFlags(&evFork, cudaEventDisableTiming);
        cudaEventCreateWithFlags(&evC, cudaEventDisableTiming);
        cudaEventCreateWithFlags(&evJoin, cudaEventDisableTiming);
    }

    // fork: stream B runs wsplit + gemm1
    cudaEventRecord(evFork, 0);
    cudaStreamWaitEvent(s2, evFork, 0);
    k_wsplit<<<(DF * HID + 255) / 256, 256, 0, s2>>>(W1);
    k_gemm1<<<NN / 64, 256, SM_TOTAL, s2>>>(x);

    // default stream: CSR build chain
    cudaMemsetAsync(deg_ptr, 0, NN * sizeof(int));
    k_hist<<<(NE + 255) / 256, 256>>>(col);
    k_scanA<<<SCAN_NB, 256>>>();
    k_scanB<<<1, 256>>>();
    k_scanC<<<SCAN_NB, 256>>>();
    cudaEventRecord(evC, 0);          // dinv ready
    k_fill<<<(NE + 255) / 256, 256>>>(row, col);

    // s2: scale mirror (needs gemm1 output + dinv), overlapped with fill
    cudaStreamWaitEvent(s2, evC, 0);
    k_scale<<<(NN * 32 + 255) / 256, 256, 0, s2>>>();
    cudaEventRecord(evJoin, s2);

    // join, then gathers
    cudaStreamWaitEvent(0, evJoin, 0);
    k_gather1<<<NN / 8, 256>>>(b1, W2);
    k_gather2<<<NN / 8, 256>>>(b2, out);
}